// round 12
// baseline (speedup 1.0000x reference)
#include <cuda_runtime.h>
#include <cstdint>
#include <cstddef>

#define NTOK 8192
#define NEXP 64
#define MDIM 2048
#define CAP  256
#define SEC  134217728LL   // 8192*64*256

#define GEMM_BLOCKS 128
#define FILL_BLOCKS 464
#define TOTAL_BLOCKS (GEMM_BLOCKS + FILL_BLOCKS)   // 592
#define CHUNK_BYTES 32768
#define CHUNK_FLOATS 8192
#define N_CHUNKS 32768                 // 2^30 bytes
#define CHUNKS_PER_BLOCK 71            // ceil(32768/464)
#define ROW_FLOATS 16384               // NEXP*CAP floats per token row

// ---------------- device scratch ----------------
__device__ int    g_e12[NTOK];           // e1 | e2<<8
__device__ float2 g_g12[NTOK];           // raw gate values (g1, g2)
__device__ int    g_loc1[NTOK];
__device__ int    g_loc2[NTOK];          // partial (needs +cnt1[e2])
__device__ int    g_cnt1[NEXP];
__device__ float  g_me_part[GEMM_BLOCKS * NEXP];
__device__ int    g_gemm_done = 0;
__device__ int    g_cs_done   = 0;
__device__ int    g_patch_done = 0;

// ---------------- threefry2x32, key (0,42), partitionable fold ----------------
__device__ __forceinline__ uint2 threefry2x32_k42(uint32_t x0, uint32_t x1) {
    const uint32_t k0 = 0u, k1 = 42u;
    const uint32_t k2 = k0 ^ k1 ^ 0x1BD11BDAu;
    x0 += k0; x1 += k1;
#define TFR(r) { x0 += x1; x1 = (x1 << (r)) | (x1 >> (32 - (r))); x1 ^= x0; }
    TFR(13) TFR(15) TFR(26) TFR(6)   x0 += k1; x1 += k2 + 1u;
    TFR(17) TFR(29) TFR(16) TFR(24)  x0 += k2; x1 += k0 + 2u;
    TFR(13) TFR(15) TFR(26) TFR(6)   x0 += k0; x1 += k1 + 3u;
    TFR(17) TFR(29) TFR(16) TFR(24)  x0 += k1; x1 += k2 + 4u;
    TFR(13) TFR(15) TFR(26) TFR(6)   x0 += k2; x1 += k0 + 5u;
#undef TFR
    return make_uint2(x0, x1);
}

__device__ __forceinline__ float gumbel_from_flat(uint32_t flat) {
    uint2 r = threefry2x32_k42(0u, flat);
    uint32_t bits = r.x ^ r.y;
    float u = __uint_as_float((bits >> 9) | 0x3f800000u) - 1.0f;
    const float tiny = 1.17549435082228751e-38f;
    u = u * (1.0f - tiny) + tiny;
    u = fmaxf(tiny, u);
    return -logf(-logf(u));
}

__device__ __forceinline__ void signal(int* ctr) {
    __threadfence();
    atomicAdd(ctr, 1);
}
__device__ __forceinline__ void spin_until(volatile int* ctr, int v) {
    while (*ctr < v) __nanosleep(1000);
    __threadfence();
}

// patch one token's possible targets inside float range [L, H) of one section
__device__ __forceinline__ void patch_token(float* __restrict__ out, int t,
                                            long long base, long long L, long long H,
                                            bool isComb) {
    int e12 = g_e12[t];
    const int e1 = e12 & 0xff, e2 = (e12 >> 8) & 0xff;
    const int l1 = g_loc1[t];
    const int l2 = g_loc2[t] + g_cnt1[e2];
    const bool k1 = (l1 < CAP), k2 = (l2 < CAP);
    float2 g12 = g_g12[t];
    const float g1 = k1 ? g12.x : 0.f;
    const float g2 = k2 ? g12.y : 0.f;
    const float denom = fmaxf(g1 + g2, 1.1920928955078125e-7f);
    if (k1) {
        long long idx = base + (long long)t * ROW_FLOATS + e1 * CAP + l1;
        if (idx >= L && idx < H) out[idx] = isComb ? (g1 / denom) : 1.0f;
    }
    if (k2) {
        long long idx = base + (long long)t * ROW_FLOATS + e2 * CAP + l2;
        if (idx >= L && idx < H) out[idx] = isComb ? (g2 / denom) : 1.0f;
    }
}

// ---------------- single mega kernel ----------------
__global__ void __launch_bounds__(256) fused_kernel(const float* __restrict__ X,
                                                    const float* __restrict__ W,
                                                    float* __restrict__ out, int out_size) {
    __shared__ float pool[8704];   // 34 KB
    const int bid = blockIdx.x;
    const int tid = threadIdx.x;
    const unsigned FULL = 0xffffffffu;
    const int w = tid >> 5;
    const int lane = tid & 31;

    // ================= FILL blocks (R4 config) + self-patch =================
    if (bid >= GEMM_BLOCKS) {
        const int fb = bid - GEMM_BLOCKS;
        if (fb == 0 && tid == 1) out[out_size - 1] = 0.f;  // 4-byte tail (outside chunks)
        float4* s4 = (float4*)pool;
        float4 z = make_float4(0.f, 0.f, 0.f, 0.f);
#pragma unroll
        for (int i = 0; i < 8; i++) s4[tid + 256 * i] = z;
        __syncthreads();

        int c0 = fb * CHUNKS_PER_BLOCK;
        int c1 = c0 + CHUNKS_PER_BLOCK;
        if (c1 > N_CHUNKS) c1 = N_CHUNKS;

        if (tid == 0) {
            asm volatile("fence.proxy.async.shared::cta;" ::: "memory");
            uint32_t saddr;
            asm("{ .reg .u64 t; cvta.to.shared.u64 t, %1; cvt.u32.u64 %0, t; }"
                : "=r"(saddr) : "l"(pool));
            for (int c = c0; c < c1; ++c) {
                char* g = (char*)out + ((long long)c << 15);
                asm volatile("cp.async.bulk.global.shared::cta.bulk_group [%0], [%1], %2;"
                             :: "l"(g), "r"(saddr), "r"((int)CHUNK_BYTES) : "memory");
                asm volatile("cp.async.bulk.commit_group;" ::: "memory");
                asm volatile("cp.async.bulk.wait_group.read 8;" ::: "memory");
            }
            asm volatile("cp.async.bulk.wait_group 0;" ::: "memory");
            asm volatile("fence.proxy.async;" ::: "memory");
            spin_until(&g_cs_done, 64);   // ready long before fill ends -> instant
        }
        __syncthreads();

        // ---- self-patch: write nonzeros that fall inside [L, H) ----
        const long long L = (long long)c0 * CHUNK_FLOATS;
        const long long H = (long long)c1 * CHUNK_FLOATS;

        // combine section: floats [1, 1+SEC)
        if (L < 1 + SEC) {
            long long lo = L > 1 ? L : 1;
            int t_lo = (int)((lo - 1) / ROW_FLOATS);
            long long hiIdx = (H < 1 + SEC ? H : 1 + SEC) - 1;  // last idx (exclusive-1)
            int t_hi = (int)((hiIdx - 1) / ROW_FLOATS);
            if (t_hi > NTOK - 1) t_hi = NTOK - 1;
            for (int t = t_lo + tid; t <= t_hi; t += 256)
                patch_token(out, t, 1LL, L, H, true);
        }
        // dispatch section: floats [1+SEC, 1+2*SEC)
        if (H > 1 + SEC) {
            const long long base = 1 + SEC;
            long long lo = L > base ? L : base;
            int t_lo = (int)((lo - base) / ROW_FLOATS);
            long long hiIdx = H - 1;
            int t_hi = (int)((hiIdx - base) / ROW_FLOATS);
            if (t_hi > NTOK - 1) t_hi = NTOK - 1;
            for (int t = t_lo + tid; t <= t_hi; t += 256)
                patch_token(out, t, base, L, H, false);
        }

        if (fb == 0) {
            // tail element (idx out_size-1, outside chunk coverage): token NTOK-1 targets
            if (tid == 0 && ((long long)out_size == 1 + 2 * SEC)) {
                patch_token(out, NTOK - 1, 1 + SEC,
                            (long long)out_size - 1, (long long)out_size, false);
            }
            // l_aux (out[0], inside chunk 0, already zero-filled by this block)
            float* sm = pool + 4096;
            if (tid < NEXP) {
                float s = 0.f;
                for (int b = 0; b < GEMM_BLOCKS; b++) s += g_me_part[b * NEXP + tid];
                float me = s * (1.0f / NTOK);
                float ce = (float)g_cnt1[tid] * (1.0f / NTOK);
                sm[tid] = me * ce;
            }
            __syncthreads();
            if (tid == 0) {
                float tot = 0.f;
                for (int i = 0; i < NEXP; i++) tot += sm[i];
                out[0] = tot * (float)NEXP;
            }
        }
        __syncthreads();
        // last fill block resets counters for next graph replay
        if (tid == 0) {
            __threadfence();
            int done = atomicAdd(&g_patch_done, 1) + 1;
            if (done == FILL_BLOCKS) {
                g_gemm_done = 0; g_cs_done = 0; g_patch_done = 0;
                __threadfence();
            }
        }
        return;
    }

    // ================= GEMM + gating (bid 0..127) =================
    {
        const int tb = bid * 64;
        const int tx = tid & 15;
        const int ty = tid >> 4;
        const int row0 = tid >> 3;
        const int row1 = (tid + 256) >> 3;
        const int kq   = (tid & 7) * 4;

        float acc[4][4];
#pragma unroll
        for (int i = 0; i < 4; i++)
#pragma unroll
            for (int j = 0; j < 4; j++) acc[i][j] = 0.f;

        float4 rx0, rx1, rw0, rw1;
        const float* Xb = X + (size_t)tb * MDIM;

#define LDG_TILE(kk)  do { \
        rx0 = *(const float4*)&Xb[(size_t)row0 * MDIM + (kk) + kq]; \
        rx1 = *(const float4*)&Xb[(size_t)row1 * MDIM + (kk) + kq]; \
        rw0 = *(const float4*)&W[(size_t)row0 * MDIM + (kk) + kq];  \
        rw1 = *(const float4*)&W[(size_t)row1 * MDIM + (kk) + kq];  \
    } while (0)

#define STS_TILE(s)   do { \
        float* sx = pool + (s) * 4352; float* sw = sx + 2176; \
        sx[(kq+0)*68+row0]=rx0.x; sx[(kq+1)*68+row0]=rx0.y; sx[(kq+2)*68+row0]=rx0.z; sx[(kq+3)*68+row0]=rx0.w; \
        sx[(kq+0)*68+row1]=rx1.x; sx[(kq+1)*68+row1]=rx1.y; sx[(kq+2)*68+row1]=rx1.z; sx[(kq+3)*68+row1]=rx1.w; \
        sw[(kq+0)*68+row0]=rw0.x; sw[(kq+1)*68+row0]=rw0.y; sw[(kq+2)*68+row0]=rw0.z; sw[(kq+3)*68+row0]=rw0.w; \
        sw[(kq+0)*68+row1]=rw1.x; sw[(kq+1)*68+row1]=rw1.y; sw[(kq+2)*68+row1]=rw1.z; sw[(kq+3)*68+row1]=rw1.w; \
    } while (0)

#define COMPUTE(s)    do { \
        const float* sx = pool + (s) * 4352; const float* sw = sx + 2176; \
        _Pragma("unroll") \
        for (int k = 0; k < 32; k++) { \
            float4 a = *(const float4*)&sx[k*68 + ty*4]; \
            float4 b = *(const float4*)&sw[k*68 + tx*4]; \
            float av[4] = {a.x, a.y, a.z, a.w}; \
            float bv[4] = {b.x, b.y, b.z, b.w}; \
            _Pragma("unroll") \
            for (int i = 0; i < 4; i++) \
            _Pragma("unroll") \
                for (int j = 0; j < 4; j++) acc[i][j] += av[i] * bv[j]; \
        } \
    } while (0)

        LDG_TILE(0);
        STS_TILE(0);
        __syncthreads();
        int s = 0;
#pragma unroll 1
        for (int kk = 32; kk < MDIM; kk += 32) {
            LDG_TILE(kk);
            COMPUTE(s);
            STS_TILE(s ^ 1);
            __syncthreads();
            s ^= 1;
        }
        COMPUTE(s);
        __syncthreads();

        float* lgs   = pool;
        float* gpart = pool + 64 * 65;
#pragma unroll
        for (int i = 0; i < 4; i++)
#pragma unroll
            for (int j = 0; j < 4; j++)
                lgs[(ty * 4 + i) * 65 + tx * 4 + j] = acc[i][j];
        __syncthreads();

        float accx = 0.f, accy = 0.f;
#pragma unroll 1
        for (int k = 0; k < 8; k++) {
            const int tl = w * 8 + k;
            const int t  = tb + tl;
            float l0 = lgs[tl * 65 + lane * 2];
            float l1 = lgs[tl * 65 + lane * 2 + 1];

            float vmax = fmaxf(l0, l1);
#pragma unroll
            for (int o = 16; o; o >>= 1) vmax = fmaxf(vmax, __shfl_xor_sync(FULL, vmax, o));

            float bv; int bi;
            if (l0 >= l1) { bv = l0; bi = lane * 2; } else { bv = l1; bi = lane * 2 + 1; }
#pragma unroll
            for (int o = 16; o; o >>= 1) {
                float ov = __shfl_xor_sync(FULL, bv, o);
                int   oi = __shfl_xor_sync(FULL, bi, o);
                if (ov > bv || (ov == bv && oi < bi)) { bv = ov; bi = oi; }
            }
            const int e1 = bi;

            float ex0 = expf(l0 - vmax), ex1 = expf(l1 - vmax);
            float ssum = ex0 + ex1;
#pragma unroll
            for (int o = 16; o; o >>= 1) ssum += __shfl_xor_sync(FULL, ssum, o);
            float gx = ex0 / ssum, gy = ex1 / ssum;
            accx += gx; accy += gy;

            uint32_t f0 = (uint32_t)t * NEXP + lane * 2;
            float n0 = l0 + gumbel_from_flat(f0);
            float n1 = l1 + gumbel_from_flat(f0 + 1);
            if (lane * 2     == e1) n0 = -__int_as_float(0x7f800000);
            if (lane * 2 + 1 == e1) n1 = -__int_as_float(0x7f800000);

            float cv; int ci;
            if (n0 >= n1) { cv = n0; ci = lane * 2; } else { cv = n1; ci = lane * 2 + 1; }
#pragma unroll
            for (int o = 16; o; o >>= 1) {
                float ov = __shfl_xor_sync(FULL, cv, o);
                int   oi = __shfl_xor_sync(FULL, ci, o);
                if (ov > cv || (ov == cv && oi < ci)) { cv = ov; ci = oi; }
            }
            const int e2 = ci;

            float ge1 = __shfl_sync(FULL, (e1 & 1) ? gy : gx, e1 >> 1);
            float ge2 = __shfl_sync(FULL, (e2 & 1) ? gy : gx, e2 >> 1);

            if (lane == 0) {
                g_e12[t] = e1 | (e2 << 8);
                g_g12[t] = make_float2(ge1, ge2);
            }
        }

        gpart[w * 64 + lane * 2]     = accx;
        gpart[w * 64 + lane * 2 + 1] = accy;
        __syncthreads();
        if (tid < NEXP) {
            float s2 = 0.f;
#pragma unroll
            for (int i = 0; i < 8; i++) s2 += gpart[i * 64 + tid];
            g_me_part[bid * NEXP + tid] = s2;
        }
        __syncthreads();
        if (tid == 0) signal(&g_gemm_done);
    }

    // blocks 64..127 exit now, freeing their SMs for the fill
    if (bid >= 64) return;

    // ================= CUMSUM in the fill's shadow (blocks 0..63) =================
    {
        const int Eid = bid;
        __shared__ int wtot[8];

        if (tid == 0) spin_until(&g_gemm_done, GEMM_BLOCKS);
        __syncthreads();

        int off1 = 0, off2 = 0;
        for (int base = 0; base < NTOK; base += 1024) {
            int4 v = *(const int4*)&g_e12[base + tid * 4];
            int va[4] = {v.x, v.y, v.z, v.w};
            int f1[4], f2[4], p1[4], p2[4];
            int c1 = 0, c2 = 0;
#pragma unroll
            for (int k = 0; k < 4; k++) {
                f1[k] = ((va[k] & 0xff) == Eid);
                f2[k] = (((va[k] >> 8) & 0xff) == Eid);
                p1[k] = c1; p2[k] = c2;
                c1 += f1[k]; c2 += f2[k];
            }
            int c = c1 | (c2 << 16);
            int incl = c;
#pragma unroll
            for (int o = 1; o < 32; o <<= 1) {
                int n = __shfl_up_sync(FULL, incl, o);
                if (lane >= o) incl += n;
            }
            int excl = incl - c;
            if (lane == 31) wtot[w] = incl;
            __syncthreads();
            int wb = 0, bt = 0;
#pragma unroll
            for (int i = 0; i < 8; i++) { int t = wtot[i]; if (i < w) wb += t; bt += t; }
            int pk = wb + excl;
            int b1 = off1 + (pk & 0xffff);
            int b2 = off2 + ((pk >> 16) & 0xffff);
#pragma unroll
            for (int k = 0; k < 4; k++) {
                int tok = base + tid * 4 + k;
                if (f1[k]) g_loc1[tok] = b1 + p1[k];
                if (f2[k]) g_loc2[tok] = b2 + p2[k];
            }
            off1 += bt & 0xffff;
            off2 += (bt >> 16) & 0xffff;
            __syncthreads();
        }
        if (tid == 0) {
            g_cnt1[Eid] = off1;
            signal(&g_cs_done);
        }
    }
}

// ---------------- launch: ONE kernel ----------------
extern "C" void kernel_launch(void* const* d_in, const int* in_sizes, int n_in,
                              void* d_out, int out_size) {
    const float* x  = (const float*)d_in[0];
    const float* wg = (const float*)d_in[1];
    float* out = (float*)d_out;
    fused_kernel<<<TOTAL_BLOCKS, 256>>>(x, wg, out, out_size);
}

// round 13
// speedup vs baseline: 1.0718x; 1.0718x over previous
#include <cuda_runtime.h>
#include <cstdint>
#include <cstddef>

#define NTOK 8192
#define NEXP 64
#define MDIM 2048
#define CAP  256
#define SEC  134217728LL   // 8192*64*256

#define GEMM_BLOCKS 128
#define FILL_BLOCKS 464
#define TOTAL_BLOCKS (GEMM_BLOCKS + FILL_BLOCKS)   // 592
#define CHUNK_BYTES 32768
#define N_CHUNKS 32768                 // 2^30 bytes
#define CHUNKS_PER_BLOCK 71            // ceil(32768/464)

// ---------------- device scratch ----------------
__device__ int    g_e12[NTOK];           // e1 | e2<<8
__device__ float2 g_g12[NTOK];           // raw gate values (g1, g2)
__device__ int    g_loc1[NTOK];
__device__ int    g_loc2[NTOK];          // partial (needs +cnt1[e2])
__device__ int    g_cnt1[NEXP];
__device__ float  g_me_part[GEMM_BLOCKS * NEXP];
__device__ int2   g_pairs[2 * NTOK];     // precomputed (rel idx, value bits); idx=-1 -> skip
__device__ float  g_laux;
__device__ int    g_gemm_done = 0;
__device__ int    g_cs_done   = 0;

// ---------------- threefry2x32, key (0,42), partitionable fold ----------------
__device__ __forceinline__ uint2 threefry2x32_k42(uint32_t x0, uint32_t x1) {
    const uint32_t k0 = 0u, k1 = 42u;
    const uint32_t k2 = k0 ^ k1 ^ 0x1BD11BDAu;
    x0 += k0; x1 += k1;
#define TFR(r) { x0 += x1; x1 = (x1 << (r)) | (x1 >> (32 - (r))); x1 ^= x0; }
    TFR(13) TFR(15) TFR(26) TFR(6)   x0 += k1; x1 += k2 + 1u;
    TFR(17) TFR(29) TFR(16) TFR(24)  x0 += k2; x1 += k0 + 2u;
    TFR(13) TFR(15) TFR(26) TFR(6)   x0 += k0; x1 += k1 + 3u;
    TFR(17) TFR(29) TFR(16) TFR(24)  x0 += k1; x1 += k2 + 4u;
    TFR(13) TFR(15) TFR(26) TFR(6)   x0 += k2; x1 += k0 + 5u;
#undef TFR
    return make_uint2(x0, x1);
}

__device__ __forceinline__ float gumbel_from_flat(uint32_t flat) {
    uint2 r = threefry2x32_k42(0u, flat);
    uint32_t bits = r.x ^ r.y;
    float u = __uint_as_float((bits >> 9) | 0x3f800000u) - 1.0f;
    const float tiny = 1.17549435082228751e-38f;
    u = u * (1.0f - tiny) + tiny;
    u = fmaxf(tiny, u);
    return -logf(-logf(u));
}

__device__ __forceinline__ void signal(int* ctr) {
    __threadfence();
    atomicAdd(ctr, 1);
}
__device__ __forceinline__ void spin_until(volatile int* ctr, int v) {
    while (*ctr < v) __nanosleep(1000);
    __threadfence();
}

// ---------------- Kernel 1: GEMM+gating + shadow cumsum/pair-precompute + TMA fill ----
__global__ void __launch_bounds__(256) fused_kernel(const float* __restrict__ X,
                                                    const float* __restrict__ W,
                                                    float* __restrict__ out, int out_size) {
    __shared__ float pool[8704];   // 34 KB
    const int bid = blockIdx.x;
    const int tid = threadIdx.x;
    const unsigned FULL = 0xffffffffu;
    const int w = tid >> 5;
    const int lane = tid & 31;

    // ================= FILL blocks (exact R4 config, untouched) =================
    if (bid >= GEMM_BLOCKS) {
        const int fb = bid - GEMM_BLOCKS;
        if (fb == 0 && tid == 1) out[out_size - 1] = 0.f;  // 4-byte tail
        float4* s4 = (float4*)pool;
        float4 z = make_float4(0.f, 0.f, 0.f, 0.f);
#pragma unroll
        for (int i = 0; i < 8; i++) s4[tid + 256 * i] = z;
        __syncthreads();
        if (tid == 0) {
            asm volatile("fence.proxy.async.shared::cta;" ::: "memory");
            uint32_t saddr;
            asm("{ .reg .u64 t; cvta.to.shared.u64 t, %1; cvt.u32.u64 %0, t; }"
                : "=r"(saddr) : "l"(pool));
            int c0 = fb * CHUNKS_PER_BLOCK;
            int c1 = c0 + CHUNKS_PER_BLOCK;
            if (c1 > N_CHUNKS) c1 = N_CHUNKS;
            for (int c = c0; c < c1; ++c) {
                char* g = (char*)out + ((long long)c << 15);
                asm volatile("cp.async.bulk.global.shared::cta.bulk_group [%0], [%1], %2;"
                             :: "l"(g), "r"(saddr), "r"((int)CHUNK_BYTES) : "memory");
                asm volatile("cp.async.bulk.commit_group;" ::: "memory");
                asm volatile("cp.async.bulk.wait_group.read 8;" ::: "memory");
            }
            asm volatile("cp.async.bulk.wait_group 0;" ::: "memory");
        }
        return;
    }

    // ================= GEMM + gating (bid 0..127) =================
    {
        const int tb = bid * 64;
        const int tx = tid & 15;
        const int ty = tid >> 4;
        const int row0 = tid >> 3;
        const int row1 = (tid + 256) >> 3;
        const int kq   = (tid & 7) * 4;

        float acc[4][4];
#pragma unroll
        for (int i = 0; i < 4; i++)
#pragma unroll
            for (int j = 0; j < 4; j++) acc[i][j] = 0.f;

        float4 rx0, rx1, rw0, rw1;
        const float* Xb = X + (size_t)tb * MDIM;

#define LDG_TILE(kk)  do { \
        rx0 = *(const float4*)&Xb[(size_t)row0 * MDIM + (kk) + kq]; \
        rx1 = *(const float4*)&Xb[(size_t)row1 * MDIM + (kk) + kq]; \
        rw0 = *(const float4*)&W[(size_t)row0 * MDIM + (kk) + kq];  \
        rw1 = *(const float4*)&W[(size_t)row1 * MDIM + (kk) + kq];  \
    } while (0)

#define STS_TILE(s)   do { \
        float* sx = pool + (s) * 4352; float* sw = sx + 2176; \
        sx[(kq+0)*68+row0]=rx0.x; sx[(kq+1)*68+row0]=rx0.y; sx[(kq+2)*68+row0]=rx0.z; sx[(kq+3)*68+row0]=rx0.w; \
        sx[(kq+0)*68+row1]=rx1.x; sx[(kq+1)*68+row1]=rx1.y; sx[(kq+2)*68+row1]=rx1.z; sx[(kq+3)*68+row1]=rx1.w; \
        sw[(kq+0)*68+row0]=rw0.x; sw[(kq+1)*68+row0]=rw0.y; sw[(kq+2)*68+row0]=rw0.z; sw[(kq+3)*68+row0]=rw0.w; \
        sw[(kq+0)*68+row1]=rw1.x; sw[(kq+1)*68+row1]=rw1.y; sw[(kq+2)*68+row1]=rw1.z; sw[(kq+3)*68+row1]=rw1.w; \
    } while (0)

#define COMPUTE(s)    do { \
        const float* sx = pool + (s) * 4352; const float* sw = sx + 2176; \
        _Pragma("unroll") \
        for (int k = 0; k < 32; k++) { \
            float4 a = *(const float4*)&sx[k*68 + ty*4]; \
            float4 b = *(const float4*)&sw[k*68 + tx*4]; \
            float av[4] = {a.x, a.y, a.z, a.w}; \
            float bv[4] = {b.x, b.y, b.z, b.w}; \
            _Pragma("unroll") \
            for (int i = 0; i < 4; i++) \
            _Pragma("unroll") \
                for (int j = 0; j < 4; j++) acc[i][j] += av[i] * bv[j]; \
        } \
    } while (0)

        LDG_TILE(0);
        STS_TILE(0);
        __syncthreads();
        int s = 0;
#pragma unroll 1
        for (int kk = 32; kk < MDIM; kk += 32) {
            LDG_TILE(kk);
            COMPUTE(s);
            STS_TILE(s ^ 1);
            __syncthreads();
            s ^= 1;
        }
        COMPUTE(s);
        __syncthreads();

        float* lgs   = pool;
        float* gpart = pool + 64 * 65;
#pragma unroll
        for (int i = 0; i < 4; i++)
#pragma unroll
            for (int j = 0; j < 4; j++)
                lgs[(ty * 4 + i) * 65 + tx * 4 + j] = acc[i][j];
        __syncthreads();

        float accx = 0.f, accy = 0.f;
#pragma unroll 1
        for (int k = 0; k < 8; k++) {
            const int tl = w * 8 + k;
            const int t  = tb + tl;
            float l0 = lgs[tl * 65 + lane * 2];
            float l1 = lgs[tl * 65 + lane * 2 + 1];

            float vmax = fmaxf(l0, l1);
#pragma unroll
            for (int o = 16; o; o >>= 1) vmax = fmaxf(vmax, __shfl_xor_sync(FULL, vmax, o));

            float bv; int bi;
            if (l0 >= l1) { bv = l0; bi = lane * 2; } else { bv = l1; bi = lane * 2 + 1; }
#pragma unroll
            for (int o = 16; o; o >>= 1) {
                float ov = __shfl_xor_sync(FULL, bv, o);
                int   oi = __shfl_xor_sync(FULL, bi, o);
                if (ov > bv || (ov == bv && oi < bi)) { bv = ov; bi = oi; }
            }
            const int e1 = bi;

            float ex0 = expf(l0 - vmax), ex1 = expf(l1 - vmax);
            float ssum = ex0 + ex1;
#pragma unroll
            for (int o = 16; o; o >>= 1) ssum += __shfl_xor_sync(FULL, ssum, o);
            float gx = ex0 / ssum, gy = ex1 / ssum;
            accx += gx; accy += gy;

            uint32_t f0 = (uint32_t)t * NEXP + lane * 2;
            float n0 = l0 + gumbel_from_flat(f0);
            float n1 = l1 + gumbel_from_flat(f0 + 1);
            if (lane * 2     == e1) n0 = -__int_as_float(0x7f800000);
            if (lane * 2 + 1 == e1) n1 = -__int_as_float(0x7f800000);

            float cv; int ci;
            if (n0 >= n1) { cv = n0; ci = lane * 2; } else { cv = n1; ci = lane * 2 + 1; }
#pragma unroll
            for (int o = 16; o; o >>= 1) {
                float ov = __shfl_xor_sync(FULL, cv, o);
                int   oi = __shfl_xor_sync(FULL, ci, o);
                if (ov > cv || (ov == cv && oi < ci)) { cv = ov; ci = oi; }
            }
            const int e2 = ci;

            float ge1 = __shfl_sync(FULL, (e1 & 1) ? gy : gx, e1 >> 1);
            float ge2 = __shfl_sync(FULL, (e2 & 1) ? gy : gx, e2 >> 1);

            if (lane == 0) {
                g_e12[t] = e1 | (e2 << 8);
                g_g12[t] = make_float2(ge1, ge2);
            }
        }

        gpart[w * 64 + lane * 2]     = accx;
        gpart[w * 64 + lane * 2 + 1] = accy;
        __syncthreads();
        if (tid < NEXP) {
            float s2 = 0.f;
#pragma unroll
            for (int i = 0; i < 8; i++) s2 += gpart[i * 64 + tid];
            g_me_part[bid * NEXP + tid] = s2;
        }
        __syncthreads();
        if (tid == 0) signal(&g_gemm_done);
    }

    if (bid >= 64) return;   // free SMs for the fill

    // ================= CUMSUM + pair precompute (blocks 0..63, in fill shadow) =====
    {
        const int Eid = bid;
        __shared__ int wtot[8];

        if (tid == 0) spin_until(&g_gemm_done, GEMM_BLOCKS);
        __syncthreads();

        int off1 = 0, off2 = 0;
        for (int base = 0; base < NTOK; base += 1024) {
            int4 v = *(const int4*)&g_e12[base + tid * 4];
            int va[4] = {v.x, v.y, v.z, v.w};
            int f1[4], f2[4], p1[4], p2[4];
            int c1 = 0, c2 = 0;
#pragma unroll
            for (int k = 0; k < 4; k++) {
                f1[k] = ((va[k] & 0xff) == Eid);
                f2[k] = (((va[k] >> 8) & 0xff) == Eid);
                p1[k] = c1; p2[k] = c2;
                c1 += f1[k]; c2 += f2[k];
            }
            int c = c1 | (c2 << 16);
            int incl = c;
#pragma unroll
            for (int o = 1; o < 32; o <<= 1) {
                int n = __shfl_up_sync(FULL, incl, o);
                if (lane >= o) incl += n;
            }
            int excl = incl - c;
            if (lane == 31) wtot[w] = incl;
            __syncthreads();
            int wb = 0, bt = 0;
#pragma unroll
            for (int i = 0; i < 8; i++) { int t = wtot[i]; if (i < w) wb += t; bt += t; }
            int pk = wb + excl;
            int b1 = off1 + (pk & 0xffff);
            int b2 = off2 + ((pk >> 16) & 0xffff);
#pragma unroll
            for (int k = 0; k < 4; k++) {
                int tok = base + tid * 4 + k;
                if (f1[k]) g_loc1[tok] = b1 + p1[k];
                if (f2[k]) g_loc2[tok] = b2 + p2[k];
            }
            off1 += bt & 0xffff;
            off2 += (bt >> 16) & 0xffff;
            __syncthreads();
        }
        if (tid == 0) {
            g_cnt1[Eid] = off1;
            signal(&g_cs_done);
            spin_until(&g_cs_done, 64);   // all cnt1/loc ready (~instant, mid-fill)
        }
        __syncthreads();

        // ---- precompute final (idx, value) pairs for tokens [Eid*128, +128) ----
        if (tid < 128) {
            const int t = Eid * 128 + tid;
            int e12 = g_e12[t];
            const int e1 = e12 & 0xff, e2 = (e12 >> 8) & 0xff;
            const int l1 = g_loc1[t];
            const int l2 = g_loc2[t] + g_cnt1[e2];
            const bool k1 = (l1 < CAP), k2 = (l2 < CAP);
            float2 g12 = g_g12[t];
            const float g1 = k1 ? g12.x : 0.f;
            const float g2 = k2 ? g12.y : 0.f;
            const float denom = fmaxf(g1 + g2, 1.1920928955078125e-7f);
            int2 pA, pB;
            pA.x = k1 ? (t * (NEXP * CAP) + e1 * CAP + l1) : -1;
            pA.y = __float_as_int(g1 / denom);
            pB.x = k2 ? (t * (NEXP * CAP) + e2 * CAP + l2) : -1;
            pB.y = __float_as_int(g2 / denom);
            *(int4*)&g_pairs[2 * t] = make_int4(pA.x, pA.y, pB.x, pB.y);
        }
        // ---- l_aux scalar (block 0) ----
        if (Eid == 0) {
            float* sm = pool;
            if (tid < NEXP) {
                float s = 0.f;
                for (int b = 0; b < GEMM_BLOCKS; b++) s += g_me_part[b * NEXP + tid];
                float me = s * (1.0f / NTOK);
                float ce = (float)g_cnt1[tid] * (1.0f / NTOK);
                sm[tid] = me * ce;
            }
            __syncthreads();
            if (tid == 0) {
                float tot = 0.f;
                for (int i = 0; i < NEXP; i++) tot += sm[i];
                g_laux = tot * (float)NEXP;
                g_gemm_done = 0; g_cs_done = 0;   // reset for next replay
                __threadfence();
            }
        }
    }
}

// ---------------- Kernel 2: replay precomputed store list ----------------
__global__ void __launch_bounds__(256) store_kernel(float* __restrict__ out, int out_size) {
    const int i = blockIdx.x * 256 + threadIdx.x;   // 0 .. 16383
    int2 p = g_pairs[i];
    const bool haveComb = ((long long)out_size >= 1 + SEC);
    const bool haveDisp = ((long long)out_size >= 1 + 2 * SEC);
    if (p.x >= 0) {
        if (haveComb) out[1 + (long long)p.x] = __int_as_float(p.y);
        if (haveDisp) out[1 + SEC + (long long)p.x] = 1.0f;
    }
    if (i == 0) out[0] = g_laux;
}

// ---------------- launch ----------------
extern "C" void kernel_launch(void* const* d_in, const int* in_sizes, int n_in,
                              void* d_out, int out_size) {
    const float* x  = (const float*)d_in[0];
    const float* wg = (const float*)d_in[1];
    float* out = (float*)d_out;

    fused_kernel<<<TOTAL_BLOCKS, 256>>>(x, wg, out, out_size);
    store_kernel<<<(2 * NTOK) / 256, 256>>>(out, out_size);
}